// round 3
// baseline (speedup 1.0000x reference)
#include <cuda_runtime.h>
#include <cuda_bf16.h>
#include <math.h>

#define NN   50000
#define EE   400000
#define ESL  (EE + NN)      // edges + self loops for GAT
#define INC  256
#define HID  128
#define H4   512
#define FCH  64
#define OUTC 2

// ---------------- scratch (device globals; no allocation allowed) ----------------
__device__ float g_yl  [NN * HID];
__device__ float g_yr  [NN * HID];
__device__ float g_deg [NN];
__device__ float g_msg [NN * HID];
__device__ float g_pre1[NN * HID];
__device__ float g_h1  [NN * HID];
__device__ float g_xh  [NN * H4];
__device__ float g_asrc[NN * 4];
__device__ float g_adst[NN * 4];
__device__ float g_m   [NN * 4];
__device__ float g_den [NN * 4];
__device__ float g_ebuf[ESL * 4];
__device__ float g_gato[NN * H4];
__device__ float g_h2  [NN * H4];
__device__ float g_y2l [NN * HID];
__device__ float g_y2r [NN * HID];
__device__ float g_msg2[NN * HID];
__device__ float g_pre3[NN * HID];
__device__ float g_h3  [NN * HID];
__device__ float g_f1p [NN * FCH];
__device__ float g_f1  [NN * FCH];
__device__ float g_stats[1024];   // [0:512) sum, [512:1024) sumsq

// ---------------- helpers ----------------
__device__ __forceinline__ void atomicMaxFloat(float* addr, float v) {
    if (v >= 0.0f) atomicMax((int*)addr, __float_as_int(v));
    else           atomicMin((unsigned int*)addr, __float_as_uint(v));
}

__device__ __forceinline__ void redAddV4(float* p, float4 v) {
    asm volatile("red.global.add.v4.f32 [%0], {%1,%2,%3,%4};"
                 :: "l"(p), "f"(v.x), "f"(v.y), "f"(v.z), "f"(v.w) : "memory");
}

// ---------------- generic fill ----------------
__global__ void fillk(float* p, float v, long n) {
    long i = (long)blockIdx.x * blockDim.x + threadIdx.x;
    long stride = (long)gridDim.x * blockDim.x;
    for (; i < n; i += stride) p[i] = v;
}

// ---------------- degree ----------------
__global__ void deg_kernel(const int* __restrict__ dst, float* deg, int E) {
    int e = blockIdx.x * blockDim.x + threadIdx.x;
    if (e < E) atomicAdd(&deg[dst[e]], 1.0f);
}

// ---------------- GEMM: C[m,n] = sum_k A[m,k] * W[n,k]  (A:[M,K], W:[Nout,K]) ----
// 128x128 tile, TK=8, 256 threads, 8x8 microtile.
__global__ void gemm_nt(const float* __restrict__ A, const float* __restrict__ W,
                        float* __restrict__ C, int M, int Nout, int K) {
    __shared__ float As[8][132];
    __shared__ float Ws[8][132];
    const int tid = threadIdx.x;
    const int m0 = blockIdx.y * 128;
    const int n0 = blockIdx.x * 128;
    const int tx = tid & 15, ty = tid >> 4;
    const int lrow = tid >> 1;
    const int lk   = (tid & 1) * 4;

    float acc[8][8];
#pragma unroll
    for (int i = 0; i < 8; i++)
#pragma unroll
        for (int j = 0; j < 8; j++) acc[i][j] = 0.0f;

    for (int k0 = 0; k0 < K; k0 += 8) {
        float4 av = make_float4(0.f, 0.f, 0.f, 0.f);
        float4 wv = make_float4(0.f, 0.f, 0.f, 0.f);
        int ar = m0 + lrow;
        if (ar < M)    av = *(const float4*)&A[(size_t)ar * K + k0 + lk];
        int wr = n0 + lrow;
        if (wr < Nout) wv = *(const float4*)&W[(size_t)wr * K + k0 + lk];
        __syncthreads();
        As[lk + 0][lrow] = av.x; As[lk + 1][lrow] = av.y;
        As[lk + 2][lrow] = av.z; As[lk + 3][lrow] = av.w;
        Ws[lk + 0][lrow] = wv.x; Ws[lk + 1][lrow] = wv.y;
        Ws[lk + 2][lrow] = wv.z; Ws[lk + 3][lrow] = wv.w;
        __syncthreads();
#pragma unroll
        for (int kk = 0; kk < 8; kk++) {
            float a[8], b[8];
            *(float4*)(a)     = *(const float4*)&As[kk][ty * 8];
            *(float4*)(a + 4) = *(const float4*)&As[kk][ty * 8 + 4];
            *(float4*)(b)     = *(const float4*)&Ws[kk][tx * 8];
            *(float4*)(b + 4) = *(const float4*)&Ws[kk][tx * 8 + 4];
#pragma unroll
            for (int i = 0; i < 8; i++)
#pragma unroll
                for (int j = 0; j < 8; j++)
                    acc[i][j] += a[i] * b[j];
        }
    }
#pragma unroll
    for (int i = 0; i < 8; i++) {
        int r = m0 + ty * 8 + i;
        if (r >= M) break;
#pragma unroll
        for (int j = 0; j < 8; j += 4) {
            int cidx = n0 + tx * 8 + j;
            if (cidx < Nout)
                *(float4*)&C[(size_t)r * Nout + cidx] =
                    make_float4(acc[i][j], acc[i][j + 1], acc[i][j + 2], acc[i][j + 3]);
        }
    }
}

// ---------------- SAGE aggregation: warp per edge, 128 channels as float4 ------
__global__ void agg128(const int* __restrict__ src, const int* __restrict__ dst,
                       const float* __restrict__ in, float* out, int E) {
    int t = blockIdx.x * blockDim.x + threadIdx.x;
    int e = t >> 5, lane = t & 31;
    if (e >= E) return;
    int s = src[e], d = dst[e];
    float4 v = *(const float4*)&in[(size_t)s * HID + lane * 4];
    redAddV4(&out[(size_t)d * HID + lane * 4], v);
}

// ---------------- SAGE pre + BN stats (C=128) ----------------
__global__ void sage_pre_stats(const float* __restrict__ msg, const float* __restrict__ yr,
                               const float* __restrict__ deg, const float* __restrict__ bias,
                               float* pre, float* gsum, float* gss, int N) {
    int c = threadIdx.x;                    // 0..127
    float bc = bias[c];
    float s = 0.f, ss = 0.f;
    for (int r = blockIdx.x; r < N; r += gridDim.x) {
        float inv = 1.0f / fmaxf(deg[r], 1.0f);
        float v = msg[(size_t)r * HID + c] * inv + bc + yr[(size_t)r * HID + c];
        pre[(size_t)r * HID + c] = v;
        s += v; ss += v * v;
    }
    atomicAdd(&gsum[c], s);
    atomicAdd(&gss[c], ss);
}

// ---------------- bias-add + BN stats (generic C) ----------------
__global__ void bias_stats(const float* __restrict__ in, const float* __restrict__ bias,
                           float* pre, float* gsum, float* gss, int N, int C) {
    int c = threadIdx.x;
    float bc = bias[c];
    float s = 0.f, ss = 0.f;
    for (int r = blockIdx.x; r < N; r += gridDim.x) {
        float v = in[(size_t)r * C + c] + bc;
        pre[(size_t)r * C + c] = v;
        s += v; ss += v * v;
    }
    atomicAdd(&gsum[c], s);
    atomicAdd(&gss[c], ss);
}

// ---------------- BN apply + ELU ----------------
__global__ void bn_elu(const float* __restrict__ pre, float* out,
                       const float* __restrict__ gsum, const float* __restrict__ gss,
                       const float* __restrict__ gamma, const float* __restrict__ beta,
                       int N, int C) {
    int c = threadIdx.x;
    const float invN = 1.0f / (float)N;
    float mean = gsum[c] * invN;
    float var  = gss[c] * invN - mean * mean;
    float sc = gamma[c] * rsqrtf(var + 1e-5f);
    float sh = beta[c] - mean * sc;
    for (int r = blockIdx.x; r < N; r += gridDim.x) {
        float v = pre[(size_t)r * C + c] * sc + sh;
        out[(size_t)r * C + c] = (v > 0.0f) ? v : expm1f(v);
    }
}

// ---------------- GAT attention coefficients: warp per (n,h) ----------------
__global__ void attn_coef(const float* __restrict__ xh, const float* __restrict__ a_s,
                          const float* __restrict__ a_d, float* asrc, float* adst, int N) {
    int gw = (blockIdx.x * blockDim.x + threadIdx.x) >> 5;
    int lane = threadIdx.x & 31;
    if (gw >= N * 4) return;
    int n = gw >> 2, h = gw & 3;
    float4 v = *(const float4*)&xh[(size_t)n * H4 + h * HID + lane * 4];
    float4 s = *(const float4*)&a_s[h * HID + lane * 4];
    float4 d = *(const float4*)&a_d[h * HID + lane * 4];
    float accs = v.x * s.x + v.y * s.y + v.z * s.z + v.w * s.w;
    float accd = v.x * d.x + v.y * d.y + v.z * d.z + v.w * d.w;
#pragma unroll
    for (int o = 16; o; o >>= 1) {
        accs += __shfl_xor_sync(0xffffffffu, accs, o);
        accd += __shfl_xor_sync(0xffffffffu, accd, o);
    }
    if (lane == 0) { asrc[n * 4 + h] = accs; adst[n * 4 + h] = accd; }
}

// ---------------- GAT pass 1: logits + segment max ----------------
__global__ void gat_max(const int* __restrict__ src, const int* __restrict__ dst,
                        const float* __restrict__ asrc, const float* __restrict__ adst,
                        float* ebuf, float* m, int E, int N) {
    int t = blockIdx.x * blockDim.x + threadIdx.x;
    int e = t >> 2, h = t & 3;
    if (e >= E + N) return;
    int s, d;
    if (e < E) { s = src[e]; d = dst[e]; } else { s = d = e - E; }
    float v = asrc[s * 4 + h] + adst[d * 4 + h];
    v = (v > 0.0f) ? v : 0.2f * v;
    ebuf[t] = v;
    atomicMaxFloat(&m[d * 4 + h], v);
}

// ---------------- GAT pass 2: exp + segment sum ----------------
__global__ void gat_den(const int* __restrict__ dst, float* ebuf,
                        const float* __restrict__ m, float* den, int E, int N) {
    int t = blockIdx.x * blockDim.x + threadIdx.x;
    int e = t >> 2, h = t & 3;
    if (e >= E + N) return;
    int d = (e < E) ? dst[e] : (e - E);
    float ex = expf(ebuf[t] - m[d * 4 + h]);
    ebuf[t] = ex;
    atomicAdd(&den[d * 4 + h], ex);
}

// ---------------- GAT pass 3: weighted aggregation (128 thr/edge) ----------------
__global__ void gat_agg(const int* __restrict__ src, const int* __restrict__ dst,
                        const float* __restrict__ xh, const float* __restrict__ ex,
                        const float* __restrict__ den, float* out, int E, int N) {
    int t = blockIdx.x * blockDim.x + threadIdx.x;
    int e = t >> 7, c = t & 127;          // c: float4 index over 512 channels
    if (e >= E + N) return;
    int s, d;
    if (e < E) { s = src[e]; d = dst[e]; } else { s = d = e - E; }
    int h = c >> 5;
    float alpha = ex[e * 4 + h] / den[d * 4 + h];
    float4 v = *(const float4*)&xh[(size_t)s * H4 + c * 4];
    v.x *= alpha; v.y *= alpha; v.z *= alpha; v.w *= alpha;
    redAddV4(&out[(size_t)d * H4 + c * 4], v);
}

// ---------------- FC2: [N,64] -> [N,2] ----------------
__global__ void fc2_kernel(const float* __restrict__ f1, const float* __restrict__ W,
                           const float* __restrict__ b, float* out, int N) {
    int n = blockIdx.x * blockDim.x + threadIdx.x;
    if (n >= N) return;
    float a0 = b[0], a1 = b[1];
#pragma unroll
    for (int k = 0; k < FCH; k++) {
        float f = f1[(size_t)n * FCH + k];
        a0 += f * W[k];
        a1 += f * W[FCH + k];
    }
    out[n * 2 + 0] = a0;
    out[n * 2 + 1] = a1;
}

// ---------------- host launcher ----------------
static inline void gemm(const float* A, const float* W, float* C, int M, int Nout, int K) {
    dim3 grid((Nout + 127) / 128, (M + 127) / 128);
    gemm_nt<<<grid, 256>>>(A, W, C, M, Nout, K);
}
static inline void fill(float* p, float v, long n) {
    long blocks = (n + 255) / 256;
    if (blocks > 131072) blocks = 131072;
    fillk<<<(int)blocks, 256>>>(p, v, n);
}

extern "C" void kernel_launch(void* const* d_in, const int* in_sizes, int n_in,
                              void* d_out, int out_size) {
    const float* x     = (const float*)d_in[0];
    const int*   ei    = (const int*)d_in[1];
    const int*   src   = ei;
    const int*   dst   = ei + EE;
    const float* W1l   = (const float*)d_in[2];
    const float* b1    = (const float*)d_in[3];
    const float* W1r   = (const float*)d_in[4];
    const float* g1    = (const float*)d_in[5];
    const float* be1   = (const float*)d_in[6];
    const float* Wg    = (const float*)d_in[7];
    const float* a_src = (const float*)d_in[8];
    const float* a_dst = (const float*)d_in[9];
    const float* gbias = (const float*)d_in[10];
    const float* g2    = (const float*)d_in[11];
    const float* be2   = (const float*)d_in[12];
    const float* W2l   = (const float*)d_in[13];
    const float* b2    = (const float*)d_in[14];
    const float* W2r   = (const float*)d_in[15];
    const float* g3    = (const float*)d_in[16];
    const float* be3   = (const float*)d_in[17];
    const float* Wf1   = (const float*)d_in[18];
    const float* bf1   = (const float*)d_in[19];
    const float* g4    = (const float*)d_in[20];
    const float* be4   = (const float*)d_in[21];
    const float* Wf2   = (const float*)d_in[22];
    const float* bf2   = (const float*)d_in[23];
    float* outp = (float*)d_out;

#define SYM(p, s) float* p; cudaGetSymbolAddress((void**)&p, s)
    SYM(yl, g_yl);   SYM(yr, g_yr);   SYM(deg, g_deg);  SYM(msg, g_msg);
    SYM(pre1, g_pre1); SYM(h1, g_h1); SYM(xh, g_xh);
    SYM(asrc, g_asrc); SYM(adst, g_adst); SYM(mx, g_m); SYM(den, g_den);
    SYM(ebuf, g_ebuf); SYM(gato, g_gato); SYM(h2, g_h2);
    SYM(y2l, g_y2l); SYM(y2r, g_y2r); SYM(msg2, g_msg2);
    SYM(pre3, g_pre3); SYM(h3, g_h3); SYM(f1p, g_f1p); SYM(f1, g_f1);
    SYM(stats, g_stats);
#undef SYM
    float* gsum = stats;
    float* gss  = stats + 512;

    const int STAT_BLOCKS = 1024;

    // ===== SAGE layer 1 =====
    fill(deg, 0.f, NN);
    fill(msg, 0.f, (long)NN * HID);
    deg_kernel<<<(EE + 255) / 256, 256>>>(dst, deg, EE);
    gemm(x, W1l, yl, NN, HID, INC);
    gemm(x, W1r, yr, NN, HID, INC);
    agg128<<<((long)EE * 32 + 255) / 256, 256>>>(src, dst, yl, msg, EE);
    fill(stats, 0.f, 1024);
    sage_pre_stats<<<STAT_BLOCKS, HID>>>(msg, yr, deg, b1, pre1, gsum, gss, NN);
    bn_elu<<<STAT_BLOCKS, HID>>>(pre1, h1, gsum, gss, g1, be1, NN, HID);

    // ===== GAT layer =====
    gemm(h1, Wg, xh, NN, H4, HID);
    attn_coef<<<((long)NN * 4 * 32 + 255) / 256, 256>>>(xh, a_src, a_dst, asrc, adst, NN);
    fill(mx, -INFINITY, (long)NN * 4);
    fill(den, 0.f, (long)NN * 4);
    fill(gato, 0.f, (long)NN * H4);
    gat_max<<<((long)ESL * 4 + 255) / 256, 256>>>(src, dst, asrc, adst, ebuf, mx, EE, NN);
    gat_den<<<((long)ESL * 4 + 255) / 256, 256>>>(dst, ebuf, mx, den, EE, NN);
    gat_agg<<<((long)ESL * 128 + 255) / 256, 256>>>(src, dst, xh, ebuf, den, gato, EE, NN);
    fill(stats, 0.f, 1024);
    bias_stats<<<STAT_BLOCKS, H4>>>(gato, gbias, gato, gsum, gss, NN, H4);
    bn_elu<<<STAT_BLOCKS, H4>>>(gato, h2, gsum, gss, g2, be2, NN, H4);

    // ===== SAGE layer 2 =====
    gemm(h2, W2l, y2l, NN, HID, H4);
    gemm(h2, W2r, y2r, NN, HID, H4);
    fill(msg2, 0.f, (long)NN * HID);
    agg128<<<((long)EE * 32 + 255) / 256, 256>>>(src, dst, y2l, msg2, EE);
    fill(stats, 0.f, 1024);
    sage_pre_stats<<<STAT_BLOCKS, HID>>>(msg2, y2r, deg, b2, pre3, gsum, gss, NN);
    bn_elu<<<STAT_BLOCKS, HID>>>(pre3, h3, gsum, gss, g3, be3, NN, HID);

    // ===== FC head =====
    gemm(h3, Wf1, f1p, NN, FCH, HID);
    fill(stats, 0.f, 1024);
    bias_stats<<<STAT_BLOCKS, FCH>>>(f1p, bf1, f1p, gsum, gss, NN, FCH);
    bn_elu<<<STAT_BLOCKS, FCH>>>(f1p, f1, gsum, gss, g4, be4, NN, FCH);
    fc2_kernel<<<(NN + 255) / 256, 256>>>(f1, Wf2, bf2, outp, NN);
}

// round 4
// speedup vs baseline: 1.5352x; 1.5352x over previous
#include <cuda_runtime.h>
#include <cuda_bf16.h>
#include <math.h>

#define NN   50000
#define EE   400000
#define ESL  (EE + NN)      // edges + self loops for GAT
#define INC  256
#define HID  128
#define H4   512
#define FCH  64
#define OUTC 2

// ---------------- scratch (device globals; no allocation allowed) ----------------
__device__ float g_yC  [NN * 256];   // [lin_l | lin_r] concat, SAGE1
__device__ float g_deg [NN];
__device__ float g_msg [NN * HID];
__device__ float g_pre1[NN * HID];
__device__ float g_h1  [NN * HID];
__device__ float g_xh  [NN * H4];
__device__ float g_asrc[NN * 4];
__device__ float g_adst[NN * 4];
__device__ float g_m   [NN * 4];
__device__ float g_den [NN * 4];
__device__ float g_ebuf[ESL * 4];
__device__ float g_gato[NN * H4];
__device__ float g_h2  [NN * H4];
__device__ float g_y2C [NN * 256];   // [lin_l | lin_r] concat, SAGE2
__device__ float g_msg2[NN * HID];
__device__ float g_pre3[NN * HID];
__device__ float g_h3  [NN * HID];
__device__ float g_f1p [NN * FCH];
__device__ float g_f1  [NN * FCH];
__device__ float g_stats[1024];      // [0:512) sum, [512:1024) sumsq
__device__ float g_wcat1[256 * INC]; // concat [W1l; W1r]
__device__ float g_wcat2[256 * H4];  // concat [W2l; W2r]

// ---------------- helpers ----------------
__device__ __forceinline__ void atomicMaxFloat(float* addr, float v) {
    if (v >= 0.0f) atomicMax((int*)addr, __float_as_int(v));
    else           atomicMin((unsigned int*)addr, __float_as_uint(v));
}

__device__ __forceinline__ void redAddV4(float* p, float4 v) {
    asm volatile("red.global.add.v4.f32 [%0], {%1,%2,%3,%4};"
                 :: "l"(p), "f"(v.x), "f"(v.y), "f"(v.z), "f"(v.w) : "memory");
}

// ---------------- generic fill ----------------
__global__ void fillk(float* p, float v, long n) {
    long i = (long)blockIdx.x * blockDim.x + threadIdx.x;
    long stride = (long)gridDim.x * blockDim.x;
    for (; i < n; i += stride) p[i] = v;
}

// ---------------- degree ----------------
__global__ void deg_kernel(const int* __restrict__ dst, float* deg, int E) {
    int e = blockIdx.x * blockDim.x + threadIdx.x;
    if (e < E) atomicAdd(&deg[dst[e]], 1.0f);
}

// =====================================================================
// Tensor-core GEMM: C[m,n] = sum_k A[m,k] * W[n,k]   (tf32 HMMA)
// Block tile 128x128, BK=16, 256 threads = 8 warps, warp tile 32x64.
// mma.sync.aligned.m16n8k8.row.col.f32.tf32.tf32.f32
// =====================================================================
#define SMP 20   // smem pitch in floats (conflict-free scalar frag reads)

#define CVT_TF32(u, f) asm("cvt.rna.tf32.f32 %0, %1;" : "=r"(u) : "f"(f))

#define MMA_TF32(c, a, b) \
    asm volatile("mma.sync.aligned.m16n8k8.row.col.f32.tf32.tf32.f32 " \
                 "{%0,%1,%2,%3}, {%4,%5,%6,%7}, {%8,%9}, {%0,%1,%2,%3};" \
                 : "+f"(c[0]), "+f"(c[1]), "+f"(c[2]), "+f"(c[3]) \
                 : "r"(a[0]), "r"(a[1]), "r"(a[2]), "r"(a[3]), \
                   "r"(b[0]), "r"(b[1]))

__global__ __launch_bounds__(256)
void gemm_tc(const float* __restrict__ A, const float* __restrict__ W,
             float* __restrict__ C, int M, int Nout, int K) {
    __shared__ unsigned int As[2][128 * SMP];
    __shared__ unsigned int Bs[2][128 * SMP];

    const int tid = threadIdx.x;
    const int m0 = blockIdx.y * 128;
    const int n0 = blockIdx.x * 128;
    const int lr = tid >> 1;             // loader row 0..127
    const int lk = (tid & 1) * 8;        // loader k offset {0,8}
    const int lane = tid & 31;
    const int warp = tid >> 5;
    const int wm = (warp & 3) * 32;      // warp M base within tile
    const int wn = (warp >> 2) * 64;     // warp N base within tile
    const int qr = lane >> 2;            // 0..7
    const int qc = lane & 3;             // 0..3

    float acc[2][8][4];
#pragma unroll
    for (int mt = 0; mt < 2; mt++)
#pragma unroll
        for (int nt = 0; nt < 8; nt++)
#pragma unroll
            for (int i = 0; i < 4; i++) acc[mt][nt][i] = 0.0f;

    const int nch = K >> 4;
    float4 av0, av1, bv0, bv1;
    const float4 z4 = make_float4(0.f, 0.f, 0.f, 0.f);

#define LOADG(ch) { \
        int kb = ((ch) << 4) + lk; \
        int ar = m0 + lr; \
        if (ar < M) { \
            const float* ap = A + (size_t)ar * K + kb; \
            av0 = *(const float4*)ap; av1 = *(const float4*)(ap + 4); \
        } else { av0 = z4; av1 = z4; } \
        int br = n0 + lr; \
        if (br < Nout) { \
            const float* bp = W + (size_t)br * K + kb; \
            bv0 = *(const float4*)bp; bv1 = *(const float4*)(bp + 4); \
        } else { bv0 = z4; bv1 = z4; } \
    }

#define STORES(bufi) { \
        uint4 ua0, ua1, ub0, ub1; \
        CVT_TF32(ua0.x, av0.x); CVT_TF32(ua0.y, av0.y); CVT_TF32(ua0.z, av0.z); CVT_TF32(ua0.w, av0.w); \
        CVT_TF32(ua1.x, av1.x); CVT_TF32(ua1.y, av1.y); CVT_TF32(ua1.z, av1.z); CVT_TF32(ua1.w, av1.w); \
        CVT_TF32(ub0.x, bv0.x); CVT_TF32(ub0.y, bv0.y); CVT_TF32(ub0.z, bv0.z); CVT_TF32(ub0.w, bv0.w); \
        CVT_TF32(ub1.x, bv1.x); CVT_TF32(ub1.y, bv1.y); CVT_TF32(ub1.z, bv1.z); CVT_TF32(ub1.w, bv1.w); \
        *(uint4*)&As[bufi][lr * SMP + lk]     = ua0; \
        *(uint4*)&As[bufi][lr * SMP + lk + 4] = ua1; \
        *(uint4*)&Bs[bufi][lr * SMP + lk]     = ub0; \
        *(uint4*)&Bs[bufi][lr * SMP + lk + 4] = ub1; \
    }

    LOADG(0);
    STORES(0);
    __syncthreads();

    int buf = 0;
    for (int ch = 0; ch < nch; ch++) {
        if (ch + 1 < nch) LOADG(ch + 1);
#pragma unroll
        for (int kk = 0; kk < 2; kk++) {
            unsigned int af[2][4], bfr[8][2];
            const int kq = kk * 8 + qc;
#pragma unroll
            for (int mt = 0; mt < 2; mt++) {
                int r = wm + mt * 16 + qr;
                af[mt][0] = As[buf][r * SMP + kq];
                af[mt][1] = As[buf][(r + 8) * SMP + kq];
                af[mt][2] = As[buf][r * SMP + kq + 4];
                af[mt][3] = As[buf][(r + 8) * SMP + kq + 4];
            }
#pragma unroll
            for (int nt = 0; nt < 8; nt++) {
                int n = wn + nt * 8 + qr;
                bfr[nt][0] = Bs[buf][n * SMP + kq];
                bfr[nt][1] = Bs[buf][n * SMP + kq + 4];
            }
#pragma unroll
            for (int mt = 0; mt < 2; mt++)
#pragma unroll
                for (int nt = 0; nt < 8; nt++)
                    MMA_TF32(acc[mt][nt], af[mt], bfr[nt]);
        }
        if (ch + 1 < nch) STORES(buf ^ 1);
        __syncthreads();
        buf ^= 1;
    }

    // epilogue
#pragma unroll
    for (int mt = 0; mt < 2; mt++) {
        int r0 = m0 + wm + mt * 16 + qr;
        int r1 = r0 + 8;
#pragma unroll
        for (int nt = 0; nt < 8; nt++) {
            int cc = n0 + wn + nt * 8 + qc * 2;
            if (cc < Nout) {
                if (r0 < M)
                    *(float2*)&C[(size_t)r0 * Nout + cc] =
                        make_float2(acc[mt][nt][0], acc[mt][nt][1]);
                if (r1 < M)
                    *(float2*)&C[(size_t)r1 * Nout + cc] =
                        make_float2(acc[mt][nt][2], acc[mt][nt][3]);
            }
        }
    }
#undef LOADG
#undef STORES
}

// ---------------- SAGE aggregation: warp per edge, 128 channels as float4 ------
__global__ void agg128(const int* __restrict__ src, const int* __restrict__ dst,
                       const float* __restrict__ in, int instride, float* out, int E) {
    int t = blockIdx.x * blockDim.x + threadIdx.x;
    int e = t >> 5, lane = t & 31;
    if (e >= E) return;
    int s = src[e], d = dst[e];
    float4 v = *(const float4*)&in[(size_t)s * instride + lane * 4];
    redAddV4(&out[(size_t)d * HID + lane * 4], v);
}

// ---------------- SAGE pre + BN stats (C=128) ----------------
__global__ void sage_pre_stats(const float* __restrict__ msg, const float* __restrict__ yr,
                               int yrstride,
                               const float* __restrict__ deg, const float* __restrict__ bias,
                               float* pre, float* gsum, float* gss, int N) {
    int c = threadIdx.x;                    // 0..127
    float bc = bias[c];
    float s = 0.f, ss = 0.f;
    for (int r = blockIdx.x; r < N; r += gridDim.x) {
        float inv = 1.0f / fmaxf(deg[r], 1.0f);
        float v = msg[(size_t)r * HID + c] * inv + bc + yr[(size_t)r * yrstride + c];
        pre[(size_t)r * HID + c] = v;
        s += v; ss += v * v;
    }
    atomicAdd(&gsum[c], s);
    atomicAdd(&gss[c], ss);
}

// ---------------- bias-add + BN stats (generic C) ----------------
__global__ void bias_stats(const float* __restrict__ in, const float* __restrict__ bias,
                           float* pre, float* gsum, float* gss, int N, int C) {
    int c = threadIdx.x;
    float bc = bias[c];
    float s = 0.f, ss = 0.f;
    for (int r = blockIdx.x; r < N; r += gridDim.x) {
        float v = in[(size_t)r * C + c] + bc;
        pre[(size_t)r * C + c] = v;
        s += v; ss += v * v;
    }
    atomicAdd(&gsum[c], s);
    atomicAdd(&gss[c], ss);
}

// ---------------- BN apply + ELU ----------------
__global__ void bn_elu(const float* __restrict__ pre, float* out,
                       const float* __restrict__ gsum, const float* __restrict__ gss,
                       const float* __restrict__ gamma, const float* __restrict__ beta,
                       int N, int C) {
    int c = threadIdx.x;
    const float invN = 1.0f / (float)N;
    float mean = gsum[c] * invN;
    float var  = gss[c] * invN - mean * mean;
    float sc = gamma[c] * rsqrtf(var + 1e-5f);
    float sh = beta[c] - mean * sc;
    for (int r = blockIdx.x; r < N; r += gridDim.x) {
        float v = pre[(size_t)r * C + c] * sc + sh;
        out[(size_t)r * C + c] = (v > 0.0f) ? v : expm1f(v);
    }
}

// ---------------- GAT attention coefficients: warp per (n,h) ----------------
__global__ void attn_coef(const float* __restrict__ xh, const float* __restrict__ a_s,
                          const float* __restrict__ a_d, float* asrc, float* adst, int N) {
    int gw = (blockIdx.x * blockDim.x + threadIdx.x) >> 5;
    int lane = threadIdx.x & 31;
    if (gw >= N * 4) return;
    int n = gw >> 2, h = gw & 3;
    float4 v = *(const float4*)&xh[(size_t)n * H4 + h * HID + lane * 4];
    float4 s = *(const float4*)&a_s[h * HID + lane * 4];
    float4 d = *(const float4*)&a_d[h * HID + lane * 4];
    float accs = v.x * s.x + v.y * s.y + v.z * s.z + v.w * s.w;
    float accd = v.x * d.x + v.y * d.y + v.z * d.z + v.w * d.w;
#pragma unroll
    for (int o = 16; o; o >>= 1) {
        accs += __shfl_xor_sync(0xffffffffu, accs, o);
        accd += __shfl_xor_sync(0xffffffffu, accd, o);
    }
    if (lane == 0) { asrc[n * 4 + h] = accs; adst[n * 4 + h] = accd; }
}

// ---------------- GAT pass 1: logits + segment max ----------------
__global__ void gat_max(const int* __restrict__ src, const int* __restrict__ dst,
                        const float* __restrict__ asrc, const float* __restrict__ adst,
                        float* ebuf, float* m, int E, int N) {
    int t = blockIdx.x * blockDim.x + threadIdx.x;
    int e = t >> 2, h = t & 3;
    if (e >= E + N) return;
    int s, d;
    if (e < E) { s = src[e]; d = dst[e]; } else { s = d = e - E; }
    float v = asrc[s * 4 + h] + adst[d * 4 + h];
    v = (v > 0.0f) ? v : 0.2f * v;
    ebuf[t] = v;
    atomicMaxFloat(&m[d * 4 + h], v);
}

// ---------------- GAT pass 2: exp + segment sum ----------------
__global__ void gat_den(const int* __restrict__ dst, float* ebuf,
                        const float* __restrict__ m, float* den, int E, int N) {
    int t = blockIdx.x * blockDim.x + threadIdx.x;
    int e = t >> 2, h = t & 3;
    if (e >= E + N) return;
    int d = (e < E) ? dst[e] : (e - E);
    float ex = expf(ebuf[t] - m[d * 4 + h]);
    ebuf[t] = ex;
    atomicAdd(&den[d * 4 + h], ex);
}

// ---------------- GAT pass 3: weighted aggregation (128 thr/edge) ----------------
__global__ void gat_agg(const int* __restrict__ src, const int* __restrict__ dst,
                        const float* __restrict__ xh, const float* __restrict__ ex,
                        const float* __restrict__ den, float* out, int E, int N) {
    int t = blockIdx.x * blockDim.x + threadIdx.x;
    int e = t >> 7, c = t & 127;          // c: float4 index over 512 channels
    if (e >= E + N) return;
    int s, d;
    if (e < E) { s = src[e]; d = dst[e]; } else { s = d = e - E; }
    int h = c >> 5;
    float alpha = ex[e * 4 + h] / den[d * 4 + h];
    float4 v = *(const float4*)&xh[(size_t)s * H4 + c * 4];
    v.x *= alpha; v.y *= alpha; v.z *= alpha; v.w *= alpha;
    redAddV4(&out[(size_t)d * H4 + c * 4], v);
}

// ---------------- FC2: [N,64] -> [N,2] ----------------
__global__ void fc2_kernel(const float* __restrict__ f1, const float* __restrict__ W,
                           const float* __restrict__ b, float* out, int N) {
    int n = blockIdx.x * blockDim.x + threadIdx.x;
    if (n >= N) return;
    float a0 = b[0], a1 = b[1];
#pragma unroll
    for (int k = 0; k < FCH; k++) {
        float f = f1[(size_t)n * FCH + k];
        a0 += f * W[k];
        a1 += f * W[FCH + k];
    }
    out[n * 2 + 0] = a0;
    out[n * 2 + 1] = a1;
}

// ---------------- host launcher ----------------
static inline void gemm(const float* A, const float* W, float* C, int M, int Nout, int K) {
    dim3 grid((Nout + 127) / 128, (M + 127) / 128);
    gemm_tc<<<grid, 256>>>(A, W, C, M, Nout, K);
}
static inline void fill(float* p, float v, long n) {
    long blocks = (n + 255) / 256;
    if (blocks > 131072) blocks = 131072;
    fillk<<<(int)blocks, 256>>>(p, v, n);
}

extern "C" void kernel_launch(void* const* d_in, const int* in_sizes, int n_in,
                              void* d_out, int out_size) {
    const float* x     = (const float*)d_in[0];
    const int*   ei    = (const int*)d_in[1];
    const int*   src   = ei;
    const int*   dst   = ei + EE;
    const float* W1l   = (const float*)d_in[2];
    const float* b1    = (const float*)d_in[3];
    const float* W1r   = (const float*)d_in[4];
    const float* g1    = (const float*)d_in[5];
    const float* be1   = (const float*)d_in[6];
    const float* Wg    = (const float*)d_in[7];
    const float* a_src = (const float*)d_in[8];
    const float* a_dst = (const float*)d_in[9];
    const float* gbias = (const float*)d_in[10];
    const float* g2    = (const float*)d_in[11];
    const float* be2   = (const float*)d_in[12];
    const float* W2l   = (const float*)d_in[13];
    const float* b2    = (const float*)d_in[14];
    const float* W2r   = (const float*)d_in[15];
    const float* g3    = (const float*)d_in[16];
    const float* be3   = (const float*)d_in[17];
    const float* Wf1   = (const float*)d_in[18];
    const float* bf1   = (const float*)d_in[19];
    const float* g4    = (const float*)d_in[20];
    const float* be4   = (const float*)d_in[21];
    const float* Wf2   = (const float*)d_in[22];
    const float* bf2   = (const float*)d_in[23];
    float* outp = (float*)d_out;

#define SYM(p, s) float* p; cudaGetSymbolAddress((void**)&p, s)
    SYM(yC, g_yC);   SYM(deg, g_deg);  SYM(msg, g_msg);
    SYM(pre1, g_pre1); SYM(h1, g_h1); SYM(xh, g_xh);
    SYM(asrc, g_asrc); SYM(adst, g_adst); SYM(mx, g_m); SYM(den, g_den);
    SYM(ebuf, g_ebuf); SYM(gato, g_gato); SYM(h2, g_h2);
    SYM(y2C, g_y2C); SYM(msg2, g_msg2);
    SYM(pre3, g_pre3); SYM(h3, g_h3); SYM(f1p, g_f1p); SYM(f1, g_f1);
    SYM(stats, g_stats); SYM(wcat1, g_wcat1); SYM(wcat2, g_wcat2);
#undef SYM
    float* gsum = stats;
    float* gss  = stats + 512;

    const int STAT_BLOCKS = 1024;

    // concat weights (async D2D copies; graph-capturable)
    cudaMemcpyAsync(wcat1,             W1l, (size_t)HID * INC * 4, cudaMemcpyDeviceToDevice);
    cudaMemcpyAsync(wcat1 + HID * INC, W1r, (size_t)HID * INC * 4, cudaMemcpyDeviceToDevice);
    cudaMemcpyAsync(wcat2,             W2l, (size_t)HID * H4 * 4, cudaMemcpyDeviceToDevice);
    cudaMemcpyAsync(wcat2 + HID * H4,  W2r, (size_t)HID * H4 * 4, cudaMemcpyDeviceToDevice);

    // ===== SAGE layer 1 =====
    fill(deg, 0.f, NN);
    fill(msg, 0.f, (long)NN * HID);
    deg_kernel<<<(EE + 255) / 256, 256>>>(dst, deg, EE);
    gemm(x, wcat1, yC, NN, 256, INC);                       // cols 0..127 = lin_l, 128..255 = lin_r
    agg128<<<((long)EE * 32 + 255) / 256, 256>>>(src, dst, yC, 256, msg, EE);
    fill(stats, 0.f, 1024);
    sage_pre_stats<<<STAT_BLOCKS, HID>>>(msg, yC + HID, 256, deg, b1, pre1, gsum, gss, NN);
    bn_elu<<<STAT_BLOCKS, HID>>>(pre1, h1, gsum, gss, g1, be1, NN, HID);

    // ===== GAT layer =====
    gemm(h1, Wg, xh, NN, H4, HID);
    attn_coef<<<((long)NN * 4 * 32 + 255) / 256, 256>>>(xh, a_src, a_dst, asrc, adst, NN);
    fill(mx, -INFINITY, (long)NN * 4);
    fill(den, 0.f, (long)NN * 4);
    fill(gato, 0.f, (long)NN * H4);
    gat_max<<<((long)ESL * 4 + 255) / 256, 256>>>(src, dst, asrc, adst, ebuf, mx, EE, NN);
    gat_den<<<((long)ESL * 4 + 255) / 256, 256>>>(dst, ebuf, mx, den, EE, NN);
    gat_agg<<<((long)ESL * 128 + 255) / 256, 256>>>(src, dst, xh, ebuf, den, gato, EE, NN);
    fill(stats, 0.f, 1024);
    bias_stats<<<STAT_BLOCKS, H4>>>(gato, gbias, gato, gsum, gss, NN, H4);
    bn_elu<<<STAT_BLOCKS, H4>>>(gato, h2, gsum, gss, g2, be2, NN, H4);

    // ===== SAGE layer 2 =====
    gemm(h2, wcat2, y2C, NN, 256, H4);                      // cols 0..127 = lin_l, 128..255 = lin_r
    fill(msg2, 0.f, (long)NN * HID);
    agg128<<<((long)EE * 32 + 255) / 256, 256>>>(src, dst, y2C, 256, msg2, EE);
    fill(stats, 0.f, 1024);
    sage_pre_stats<<<STAT_BLOCKS, HID>>>(msg2, y2C + HID, 256, deg, b2, pre3, gsum, gss, NN);
    bn_elu<<<STAT_BLOCKS, HID>>>(pre3, h3, gsum, gss, g3, be3, NN, HID);

    // ===== FC head =====
    gemm(h3, Wf1, f1p, NN, FCH, HID);
    fill(stats, 0.f, 1024);
    bias_stats<<<STAT_BLOCKS, FCH>>>(f1p, bf1, f1p, gsum, gss, NN, FCH);
    bn_elu<<<STAT_BLOCKS, FCH>>>(f1p, f1, gsum, gss, g4, be4, NN, FCH);
    fc2_kernel<<<(NN + 255) / 256, 256>>>(f1, Wf2, bf2, outp, NN);
}

// round 5
// speedup vs baseline: 2.2516x; 1.4667x over previous
#include <cuda_runtime.h>
#include <cuda_bf16.h>
#include <math.h>

#define NN   50000
#define EE   400000
#define INC  256
#define HID  128
#define H4   512
#define FCH  64
#define OUTC 2
#define GCAP 256   // smem exp cache per head in gat_fused

// ---------------- scratch (device globals; no allocation allowed) ----------------
__device__ float g_yC  [NN * 256];   // [lin_l | lin_r] concat, SAGE1
__device__ float g_pre1[NN * HID];
__device__ float g_h1  [NN * HID];
__device__ float g_xh  [NN * H4];
__device__ float g_asrc[NN * 4];
__device__ float g_adst[NN * 4];
__device__ float g_pre2[NN * H4];
__device__ float g_h2  [NN * H4];
__device__ float g_y2C [NN * 256];   // [lin_l | lin_r] concat, SAGE2
__device__ float g_pre3[NN * HID];
__device__ float g_h3  [NN * HID];
__device__ float g_f1p [NN * FCH];
__device__ float g_f1  [NN * FCH];
__device__ float g_stats[1024];      // [0:512) sum, [512:1024) sumsq
__device__ float g_wcat1[256 * INC];
__device__ float g_wcat2[256 * H4];
__device__ int   g_rowptr[NN + 1];
__device__ int   g_cnt [NN];
__device__ int   g_cnt2[NN];
__device__ int   g_csrc[EE];         // CSR: src node per slot, grouped by dst

// ---------------- generic fill ----------------
__global__ void fillk(float* p, float v, long n) {
    long i = (long)blockIdx.x * blockDim.x + threadIdx.x;
    long stride = (long)gridDim.x * blockDim.x;
    for (; i < n; i += stride) p[i] = v;
}

// ---------------- CSR build ----------------
__global__ void count_kernel(const int* __restrict__ dst, int* cnt, int E) {
    int e = blockIdx.x * blockDim.x + threadIdx.x;
    if (e < E) atomicAdd(&cnt[dst[e]], 1);
}

__global__ void scan_kernel(const int* __restrict__ cnt, int* rowptr) {
    __shared__ int s[1024];
    const int CH = (NN + 1023) / 1024;
    int t = threadIdx.x;
    int b0 = t * CH;
    int sum = 0;
    for (int j = 0; j < CH; j++) {
        int idx = b0 + j;
        if (idx < NN) sum += cnt[idx];
    }
    s[t] = sum;
    __syncthreads();
    for (int off = 1; off < 1024; off <<= 1) {
        int v = (t >= off) ? s[t - off] : 0;
        __syncthreads();
        s[t] += v;
        __syncthreads();
    }
    int run = (t == 0) ? 0 : s[t - 1];
    for (int j = 0; j < CH; j++) {
        int idx = b0 + j;
        if (idx < NN) { rowptr[idx] = run; run += cnt[idx]; }
    }
    if (t == 1023) rowptr[NN] = run;
}

__global__ void scatter_kernel(const int* __restrict__ src, const int* __restrict__ dst,
                               const int* __restrict__ rowptr, int* cnt2, int* csrc, int E) {
    int e = blockIdx.x * blockDim.x + threadIdx.x;
    if (e >= E) return;
    int d = dst[e];
    int pos = rowptr[d] + atomicAdd(&cnt2[d], 1);
    csrc[pos] = src[e];
}

// =====================================================================
// Tensor-core GEMM: C[m,n] = sum_k A[m,k] * W[n,k]   (tf32 HMMA)
// =====================================================================
#define SMP 20

#define CVT_TF32(u, f) asm("cvt.rna.tf32.f32 %0, %1;" : "=r"(u) : "f"(f))

#define MMA_TF32(c, a, b) \
    asm volatile("mma.sync.aligned.m16n8k8.row.col.f32.tf32.tf32.f32 " \
                 "{%0,%1,%2,%3}, {%4,%5,%6,%7}, {%8,%9}, {%0,%1,%2,%3};" \
                 : "+f"(c[0]), "+f"(c[1]), "+f"(c[2]), "+f"(c[3]) \
                 : "r"(a[0]), "r"(a[1]), "r"(a[2]), "r"(a[3]), \
                   "r"(b[0]), "r"(b[1]))

__global__ __launch_bounds__(256)
void gemm_tc(const float* __restrict__ A, const float* __restrict__ W,
             float* __restrict__ C, int M, int Nout, int K) {
    __shared__ unsigned int As[2][128 * SMP];
    __shared__ unsigned int Bs[2][128 * SMP];

    const int tid = threadIdx.x;
    const int m0 = blockIdx.y * 128;
    const int n0 = blockIdx.x * 128;
    const int lr = tid >> 1;
    const int lk = (tid & 1) * 8;
    const int lane = tid & 31;
    const int warp = tid >> 5;
    const int wm = (warp & 3) * 32;
    const int wn = (warp >> 2) * 64;
    const int qr = lane >> 2;
    const int qc = lane & 3;

    float acc[2][8][4];
#pragma unroll
    for (int mt = 0; mt < 2; mt++)
#pragma unroll
        for (int nt = 0; nt < 8; nt++)
#pragma unroll
            for (int i = 0; i < 4; i++) acc[mt][nt][i] = 0.0f;

    const int nch = K >> 4;
    float4 av0, av1, bv0, bv1;
    const float4 z4 = make_float4(0.f, 0.f, 0.f, 0.f);

#define LOADG(ch) { \
        int kb = ((ch) << 4) + lk; \
        int ar = m0 + lr; \
        if (ar < M) { \
            const float* ap = A + (size_t)ar * K + kb; \
            av0 = *(const float4*)ap; av1 = *(const float4*)(ap + 4); \
        } else { av0 = z4; av1 = z4; } \
        int br = n0 + lr; \
        if (br < Nout) { \
            const float* bp = W + (size_t)br * K + kb; \
            bv0 = *(const float4*)bp; bv1 = *(const float4*)(bp + 4); \
        } else { bv0 = z4; bv1 = z4; } \
    }

#define STORES(bufi) { \
        uint4 ua0, ua1, ub0, ub1; \
        CVT_TF32(ua0.x, av0.x); CVT_TF32(ua0.y, av0.y); CVT_TF32(ua0.z, av0.z); CVT_TF32(ua0.w, av0.w); \
        CVT_TF32(ua1.x, av1.x); CVT_TF32(ua1.y, av1.y); CVT_TF32(ua1.z, av1.z); CVT_TF32(ua1.w, av1.w); \
        CVT_TF32(ub0.x, bv0.x); CVT_TF32(ub0.y, bv0.y); CVT_TF32(ub0.z, bv0.z); CVT_TF32(ub0.w, bv0.w); \
        CVT_TF32(ub1.x, bv1.x); CVT_TF32(ub1.y, bv1.y); CVT_TF32(ub1.z, bv1.z); CVT_TF32(ub1.w, bv1.w); \
        *(uint4*)&As[bufi][lr * SMP + lk]     = ua0; \
        *(uint4*)&As[bufi][lr * SMP + lk + 4] = ua1; \
        *(uint4*)&Bs[bufi][lr * SMP + lk]     = ub0; \
        *(uint4*)&Bs[bufi][lr * SMP + lk + 4] = ub1; \
    }

    LOADG(0);
    STORES(0);
    __syncthreads();

    int buf = 0;
    for (int ch = 0; ch < nch; ch++) {
        if (ch + 1 < nch) LOADG(ch + 1);
#pragma unroll
        for (int kk = 0; kk < 2; kk++) {
            unsigned int af[2][4], bfr[8][2];
            const int kq = kk * 8 + qc;
#pragma unroll
            for (int mt = 0; mt < 2; mt++) {
                int r = wm + mt * 16 + qr;
                af[mt][0] = As[buf][r * SMP + kq];
                af[mt][1] = As[buf][(r + 8) * SMP + kq];
                af[mt][2] = As[buf][r * SMP + kq + 4];
                af[mt][3] = As[buf][(r + 8) * SMP + kq + 4];
            }
#pragma unroll
            for (int nt = 0; nt < 8; nt++) {
                int n = wn + nt * 8 + qr;
                bfr[nt][0] = Bs[buf][n * SMP + kq];
                bfr[nt][1] = Bs[buf][n * SMP + kq + 4];
            }
#pragma unroll
            for (int mt = 0; mt < 2; mt++)
#pragma unroll
                for (int nt = 0; nt < 8; nt++)
                    MMA_TF32(acc[mt][nt], af[mt], bfr[nt]);
        }
        if (ch + 1 < nch) STORES(buf ^ 1);
        __syncthreads();
        buf ^= 1;
    }

#pragma unroll
    for (int mt = 0; mt < 2; mt++) {
        int r0 = m0 + wm + mt * 16 + qr;
        int r1 = r0 + 8;
#pragma unroll
        for (int nt = 0; nt < 8; nt++) {
            int cc = n0 + wn + nt * 8 + qc * 2;
            if (cc < Nout) {
                if (r0 < M)
                    *(float2*)&C[(size_t)r0 * Nout + cc] =
                        make_float2(acc[mt][nt][0], acc[mt][nt][1]);
                if (r1 < M)
                    *(float2*)&C[(size_t)r1 * Nout + cc] =
                        make_float2(acc[mt][nt][2], acc[mt][nt][3]);
            }
        }
    }
#undef LOADG
#undef STORES
}

// ---------------- SAGE fused aggregation: warp per node (CSR gather) ----------
// pre = mean_{j->i} yl[j] + bias + yr[i], where yC = [yl | yr] (stride 256)
__global__ void sage_agg(const int* __restrict__ rowptr, const int* __restrict__ csrc,
                         const float* __restrict__ yC, const float* __restrict__ bias,
                         float* __restrict__ pre) {
    int w = (blockIdx.x * blockDim.x + threadIdx.x) >> 5;
    int lane = threadIdx.x & 31;
    if (w >= NN) return;
    int beg = rowptr[w], end = rowptr[w + 1];
    float4 acc = make_float4(0.f, 0.f, 0.f, 0.f);
    for (int p = beg; p < end; p++) {
        int s = csrc[p];
        float4 v = *(const float4*)&yC[(size_t)s * 256 + lane * 4];
        acc.x += v.x; acc.y += v.y; acc.z += v.z; acc.w += v.w;
    }
    float inv = 1.0f / fmaxf((float)(end - beg), 1.0f);
    float4 r = *(const float4*)&yC[(size_t)w * 256 + 128 + lane * 4];
    float4 b = *(const float4*)&bias[lane * 4];
    float4 o;
    o.x = acc.x * inv + b.x + r.x;
    o.y = acc.y * inv + b.y + r.y;
    o.z = acc.z * inv + b.z + r.z;
    o.w = acc.w * inv + b.w + r.w;
    *(float4*)&pre[(size_t)w * HID + lane * 4] = o;
}

// ---------------- GAT attention coefficients: warp per (n,h) ----------------
__global__ void attn_coef(const float* __restrict__ xh, const float* __restrict__ a_s,
                          const float* __restrict__ a_d, float* asrc, float* adst, int N) {
    int gw = (blockIdx.x * blockDim.x + threadIdx.x) >> 5;
    int lane = threadIdx.x & 31;
    if (gw >= N * 4) return;
    int n = gw >> 2, h = gw & 3;
    float4 v = *(const float4*)&xh[(size_t)n * H4 + h * HID + lane * 4];
    float4 s = *(const float4*)&a_s[h * HID + lane * 4];
    float4 d = *(const float4*)&a_d[h * HID + lane * 4];
    float accs = v.x * s.x + v.y * s.y + v.z * s.z + v.w * s.w;
    float accd = v.x * d.x + v.y * d.y + v.z * d.z + v.w * d.w;
#pragma unroll
    for (int o = 16; o; o >>= 1) {
        accs += __shfl_xor_sync(0xffffffffu, accs, o);
        accd += __shfl_xor_sync(0xffffffffu, accd, o);
    }
    if (lane == 0) { asrc[n * 4 + h] = accs; adst[n * 4 + h] = accd; }
}

// ---------------- GAT fused: block (128 thr) per node ----------------
// Self-loop included. pre = segment_softmax-weighted sum of xh[src] + gbias.
__global__ __launch_bounds__(128)
void gat_fused(const int* __restrict__ rowptr, const int* __restrict__ csrc,
               const float* __restrict__ asrc, const float* __restrict__ adst,
               const float* __restrict__ xh, const float* __restrict__ gbias,
               float* __restrict__ pre) {
    __shared__ float s_mx[4], s_den[4], s_self[4];
    __shared__ float s_ex[GCAP * 4];
    int i = blockIdx.x;
    int tid = threadIdx.x;
    int beg = rowptr[i], end = rowptr[i + 1];
    int deg = end - beg;

    if (tid < 4) {
        int h = tid;
        float ad = adst[i * 4 + h];
        float vs = asrc[i * 4 + h] + ad;
        vs = (vs > 0.f) ? vs : 0.2f * vs;              // self-loop logit
        float mx = vs;
        for (int p = beg; p < end; p++) {
            float v = asrc[csrc[p] * 4 + h] + ad;
            v = (v > 0.f) ? v : 0.2f * v;
            mx = fmaxf(mx, v);
        }
        float den = expf(vs - mx);
        s_self[h] = den;
        for (int e = 0; e < deg; e++) {
            float v = asrc[csrc[beg + e] * 4 + h] + ad;
            v = (v > 0.f) ? v : 0.2f * v;
            float ex = expf(v - mx);
            if (e < GCAP) s_ex[e * 4 + h] = ex;
            den += ex;
        }
        s_mx[h] = mx;
        s_den[h] = den;
    }
    __syncthreads();

    int c = tid;              // float4 channel index 0..127 over 512 channels
    int h = c >> 5;
    float invden = 1.0f / s_den[h];
    float mx = s_mx[h];
    float ad = adst[i * 4 + h];

    float al = s_self[h] * invden;
    float4 v = *(const float4*)&xh[(size_t)i * H4 + c * 4];
    float4 acc;
    acc.x = al * v.x; acc.y = al * v.y; acc.z = al * v.z; acc.w = al * v.w;

    for (int e = 0; e < deg; e++) {
        int s = csrc[beg + e];
        float ex;
        if (e < GCAP) ex = s_ex[e * 4 + h];
        else {
            float lv = asrc[s * 4 + h] + ad;
            lv = (lv > 0.f) ? lv : 0.2f * lv;
            ex = expf(lv - mx);
        }
        float a = ex * invden;
        float4 u = *(const float4*)&xh[(size_t)s * H4 + c * 4];
        acc.x += a * u.x; acc.y += a * u.y; acc.z += a * u.z; acc.w += a * u.w;
    }
    float4 b = *(const float4*)&gbias[c * 4];
    acc.x += b.x; acc.y += b.y; acc.z += b.z; acc.w += b.w;
    *(float4*)&pre[(size_t)i * H4 + c * 4] = acc;
}

// ---------------- BN stats (pre already includes bias) ----------------
__global__ void stats_only(const float* __restrict__ pre,
                           float* gsum, float* gss, int N, int C) {
    int c = threadIdx.x;
    float s = 0.f, ss = 0.f;
    for (int r = blockIdx.x; r < N; r += gridDim.x) {
        float v = pre[(size_t)r * C + c];
        s += v; ss += v * v;
    }
    atomicAdd(&gsum[c], s);
    atomicAdd(&gss[c], ss);
}

// ---------------- bias-add + BN stats (FC1) ----------------
__global__ void bias_stats(const float* __restrict__ in, const float* __restrict__ bias,
                           float* pre, float* gsum, float* gss, int N, int C) {
    int c = threadIdx.x;
    float bc = bias[c];
    float s = 0.f, ss = 0.f;
    for (int r = blockIdx.x; r < N; r += gridDim.x) {
        float v = in[(size_t)r * C + c] + bc;
        pre[(size_t)r * C + c] = v;
        s += v; ss += v * v;
    }
    atomicAdd(&gsum[c], s);
    atomicAdd(&gss[c], ss);
}

// ---------------- BN apply + ELU ----------------
__global__ void bn_elu(const float* __restrict__ pre, float* out,
                       const float* __restrict__ gsum, const float* __restrict__ gss,
                       const float* __restrict__ gamma, const float* __restrict__ beta,
                       int N, int C) {
    int c = threadIdx.x;
    const float invN = 1.0f / (float)N;
    float mean = gsum[c] * invN;
    float var  = gss[c] * invN - mean * mean;
    float sc = gamma[c] * rsqrtf(var + 1e-5f);
    float sh = beta[c] - mean * sc;
    for (int r = blockIdx.x; r < N; r += gridDim.x) {
        float v = pre[(size_t)r * C + c] * sc + sh;
        out[(size_t)r * C + c] = (v > 0.0f) ? v : expm1f(v);
    }
}

// ---------------- FC2: [N,64] -> [N,2] ----------------
__global__ void fc2_kernel(const float* __restrict__ f1, const float* __restrict__ W,
                           const float* __restrict__ b, float* out, int N) {
    int n = blockIdx.x * blockDim.x + threadIdx.x;
    if (n >= N) return;
    float a0 = b[0], a1 = b[1];
#pragma unroll
    for (int k = 0; k < FCH; k++) {
        float f = f1[(size_t)n * FCH + k];
        a0 += f * W[k];
        a1 += f * W[FCH + k];
    }
    out[n * 2 + 0] = a0;
    out[n * 2 + 1] = a1;
}

// ---------------- host launcher ----------------
static inline void gemm(const float* A, const float* W, float* C, int M, int Nout, int K) {
    dim3 grid((Nout + 127) / 128, (M + 127) / 128);
    gemm_tc<<<grid, 256>>>(A, W, C, M, Nout, K);
}
static inline void fill(float* p, float v, long n) {
    long blocks = (n + 255) / 256;
    if (blocks > 131072) blocks = 131072;
    fillk<<<(int)blocks, 256>>>(p, v, n);
}

extern "C" void kernel_launch(void* const* d_in, const int* in_sizes, int n_in,
                              void* d_out, int out_size) {
    const float* x     = (const float*)d_in[0];
    const int*   ei    = (const int*)d_in[1];
    const int*   src   = ei;
    const int*   dst   = ei + EE;
    const float* W1l   = (const float*)d_in[2];
    const float* b1    = (const float*)d_in[3];
    const float* W1r   = (const float*)d_in[4];
    const float* g1    = (const float*)d_in[5];
    const float* be1   = (const float*)d_in[6];
    const float* Wg    = (const float*)d_in[7];
    const float* a_src = (const float*)d_in[8];
    const float* a_dst = (const float*)d_in[9];
    const float* gbias = (const float*)d_in[10];
    const float* g2    = (const float*)d_in[11];
    const float* be2   = (const float*)d_in[12];
    const float* W2l   = (const float*)d_in[13];
    const float* b2    = (const float*)d_in[14];
    const float* W2r   = (const float*)d_in[15];
    const float* g3    = (const float*)d_in[16];
    const float* be3   = (const float*)d_in[17];
    const float* Wf1   = (const float*)d_in[18];
    const float* bf1   = (const float*)d_in[19];
    const float* g4    = (const float*)d_in[20];
    const float* be4   = (const float*)d_in[21];
    const float* Wf2   = (const float*)d_in[22];
    const float* bf2   = (const float*)d_in[23];
    float* outp = (float*)d_out;

#define SYM(T, p, s) T* p; cudaGetSymbolAddress((void**)&p, s)
    SYM(float, yC, g_yC);
    SYM(float, pre1, g_pre1); SYM(float, h1, g_h1); SYM(float, xh, g_xh);
    SYM(float, asrc, g_asrc); SYM(float, adst, g_adst);
    SYM(float, pre2, g_pre2); SYM(float, h2, g_h2);
    SYM(float, y2C, g_y2C);
    SYM(float, pre3, g_pre3); SYM(float, h3, g_h3);
    SYM(float, f1p, g_f1p); SYM(float, f1, g_f1);
    SYM(float, stats, g_stats);
    SYM(float, wcat1, g_wcat1); SYM(float, wcat2, g_wcat2);
    SYM(int, rowptr, g_rowptr); SYM(int, cnt, g_cnt);
    SYM(int, cnt2, g_cnt2); SYM(int, csrc, g_csrc);
#undef SYM
    float* gsum = stats;
    float* gss  = stats + 512;
    const int STAT_BLOCKS = 1024;

    // weight concat (D2D async; graph-capturable)
    cudaMemcpyAsync(wcat1,             W1l, (size_t)HID * INC * 4, cudaMemcpyDeviceToDevice);
    cudaMemcpyAsync(wcat1 + HID * INC, W1r, (size_t)HID * INC * 4, cudaMemcpyDeviceToDevice);
    cudaMemcpyAsync(wcat2,             W2l, (size_t)HID * H4 * 4, cudaMemcpyDeviceToDevice);
    cudaMemcpyAsync(wcat2 + HID * H4,  W2r, (size_t)HID * H4 * 4, cudaMemcpyDeviceToDevice);

    // ===== CSR build =====
    fill((float*)cnt, 0.f, NN);
    fill((float*)cnt2, 0.f, NN);
    count_kernel<<<(EE + 255) / 256, 256>>>(dst, cnt, EE);
    scan_kernel<<<1, 1024>>>(cnt, rowptr);
    scatter_kernel<<<(EE + 255) / 256, 256>>>(src, dst, rowptr, cnt2, csrc, EE);

    // ===== SAGE layer 1 =====
    gemm(x, wcat1, yC, NN, 256, INC);
    sage_agg<<<(NN * 32 + 255) / 256, 256>>>(rowptr, csrc, yC, b1, pre1);
    fill(stats, 0.f, 1024);
    stats_only<<<STAT_BLOCKS, HID>>>(pre1, gsum, gss, NN, HID);
    bn_elu<<<STAT_BLOCKS, HID>>>(pre1, h1, gsum, gss, g1, be1, NN, HID);

    // ===== GAT layer =====
    gemm(h1, Wg, xh, NN, H4, HID);
    attn_coef<<<(NN * 4 * 32 + 255) / 256, 256>>>(xh, a_src, a_dst, asrc, adst, NN);
    gat_fused<<<NN, 128>>>(rowptr, csrc, asrc, adst, xh, gbias, pre2);
    fill(stats, 0.f, 1024);
    stats_only<<<STAT_BLOCKS, H4>>>(pre2, gsum, gss, NN, H4);
    bn_elu<<<STAT_BLOCKS, H4>>>(pre2, h2, gsum, gss, g2, be2, NN, H4);

    // ===== SAGE layer 2 =====
    gemm(h2, wcat2, y2C, NN, 256, H4);
    sage_agg<<<(NN * 32 + 255) / 256, 256>>>(rowptr, csrc, y2C, b2, pre3);
    fill(stats, 0.f, 1024);
    stats_only<<<STAT_BLOCKS, HID>>>(pre3, gsum, gss, NN, HID);
    bn_elu<<<STAT_BLOCKS, HID>>>(pre3, h3, gsum, gss, g3, be3, NN, HID);

    // ===== FC head =====
    gemm(h3, Wf1, f1p, NN, FCH, HID);
    fill(stats, 0.f, 1024);
    bias_stats<<<STAT_BLOCKS, FCH>>>(f1p, bf1, f1p, gsum, gss, NN, FCH);
    bn_elu<<<STAT_BLOCKS, FCH>>>(f1p, f1, gsum, gss, g4, be4, NN, FCH);
    fc2_kernel<<<(NN + 255) / 256, 256>>>(f1, Wf2, bf2, outp, NN);
}